// round 13
// baseline (speedup 1.0000x reference)
#include <cuda_runtime.h>
#include <cuda_fp16.h>
#include <cstdint>

#define MAX_NODES 100000
#define UNITS 128

// ---------------------------------------------------------------------------
// Scratch (no cudaMalloc allowed)
// ---------------------------------------------------------------------------
__device__ __align__(16) float g_h[(size_t)MAX_NODES * UNITS];  // 51.2 MB
__device__ int   g_row_ptr[MAX_NODES + 1];
__device__ int   g_idx64;
// W split into fp16 hi/lo, stored as B[n][k] = W[k][n], row-major [128][128]
__device__ __align__(16) unsigned short g_whi[128 * 128];
__device__ __align__(16) unsigned short g_wlo[128 * 128];

__device__ __forceinline__ uint32_t smem_u32(const void* p) {
    uint32_t a;
    asm("{ .reg .u64 t; cvta.to.shared.u64 t, %1; cvt.u32.u64 %0, t; }"
        : "=r"(a) : "l"(p));
    return a;
}

__device__ __forceinline__ uint32_t h2_as_u32(__half2 h) {
    union { __half2 h; uint32_t u; } cvt;
    cvt.h = h;
    return cvt.u;
}

template <int IS64>
__device__ __forceinline__ int load_idx(const void* p, int i) {
    if (IS64) return (int)__ldg(((const long long*)p) + i);
    return __ldg(((const int*)p) + i);
}

// ---------------------------------------------------------------------------
// Fused prep: W split into fp16 hi/lo images B[n][k]  +  index-dtype probe.
// ---------------------------------------------------------------------------
__global__ void prep_kernel(const float* __restrict__ W, const int* __restrict__ ec) {
    if (blockIdx.x == 0 && threadIdx.x == 0) {
        int nz = 0;
        #pragma unroll
        for (int i = 1; i < 64; i += 2) nz += (ec[i] != 0);
        g_idx64 = (nz == 0) ? 1 : 0;
    }
    int i = blockIdx.x * blockDim.x + threadIdx.x;
    if (i >= 128 * 128) return;
    int n = i >> 7, k = i & 127;
    float w = __ldg(W + (size_t)k * 128 + n);
    __half hi = __float2half_rn(w);
    float r = w - __half2float(hi);
    g_whi[n * 128 + k] = __half_as_ushort(hi);
    g_wlo[n * 128 + k] = __half_as_ushort(__float2half_rn(r));
}

// ---------------------------------------------------------------------------
// CSR row_ptr via edge-difference scatter (one pass, coalesced).
// ---------------------------------------------------------------------------
template <int IS64>
__device__ __forceinline__ void rowptr_body(const void* er, int E, int M) {
    int i = blockIdx.x * blockDim.x + threadIdx.x;
    if (i > E) return;
    if (i == E) {
        int last = load_idx<IS64>(er, E - 1);
        for (int r = last + 1; r <= M; r++) g_row_ptr[r] = E;
        return;
    }
    int r1 = load_idx<IS64>(er, i);
    int r0 = (i == 0) ? -1 : load_idx<IS64>(er, i - 1);
    for (int r = r0 + 1; r <= r1; r++) g_row_ptr[r] = i;
}

__global__ void rowptr_kernel(const void* __restrict__ er, int E, int M) {
    if (g_idx64) rowptr_body<1>(er, E, M);
    else         rowptr_body<0>(er, E, M);
}

// ---------------------------------------------------------------------------
// HMMA GEMM: g_h[M,128] = X[M,128] @ W[128,128]
// fp16 2-pass split (xhi*whi + xhi*wlo), fp32 accum, mma.sync.m16n8k16.
// CTA tile 128x128, 256 threads = 8 warps (4m x 2n). smem 104.4KB -> 2 CTA/SM.
// X DRAM loads issued FIRST so their latency hides behind W (L2) staging.
// ---------------------------------------------------------------------------
#define LDS_STRIDE 136                  // 272B rows = 17*16B, conflict-free
#define TILE_BYTES (128 * LDS_STRIDE * 2)
#define SM_XHI 0
#define SM_WHI (SM_XHI + TILE_BYTES)
#define SM_WLO (SM_WHI + TILE_BYTES)
#define SM_TOTAL (SM_WLO + TILE_BYTES)

__device__ __forceinline__ void ldsm_x4(uint32_t* r, uint32_t addr) {
    asm volatile("ldmatrix.sync.aligned.m8n8.x4.shared.b16 {%0,%1,%2,%3}, [%4];"
                 : "=r"(r[0]), "=r"(r[1]), "=r"(r[2]), "=r"(r[3]) : "r"(addr));
}
__device__ __forceinline__ void mma_fp16(float* c, const uint32_t* a, const uint32_t* b) {
    asm volatile(
        "mma.sync.aligned.m16n8k16.row.col.f32.f16.f16.f32 "
        "{%0,%1,%2,%3}, {%4,%5,%6,%7}, {%8,%9}, {%0,%1,%2,%3};"
        : "+f"(c[0]), "+f"(c[1]), "+f"(c[2]), "+f"(c[3])
        : "r"(a[0]), "r"(a[1]), "r"(a[2]), "r"(a[3]), "r"(b[0]), "r"(b[1]));
}

__global__ __launch_bounds__(256, 2)
void gemm_hmma_kernel(const float* __restrict__ X, int M)
{
    extern __shared__ char smem[];
    const uint32_t sb = smem_u32(smem);
    const int tid = threadIdx.x;
    const int wid = tid >> 5, lane = tid & 31;
    const int m0 = blockIdx.x * 128;

    // ---- issue X DRAM loads first (16 float4 in flight) ----
    float4 xv[16];
    {
        int row = tid >> 1, k0 = (tid & 1) * 64;
        bool valid = (m0 + row) < M;
        const float* xp = X + (size_t)(m0 + row) * 128 + k0;
        #pragma unroll
        for (int j = 0; j < 8; j++) {
            xv[2 * j]     = make_float4(0, 0, 0, 0);
            xv[2 * j + 1] = make_float4(0, 0, 0, 0);
            if (valid) {
                xv[2 * j]     = __ldg((const float4*)(xp + j * 8));
                xv[2 * j + 1] = __ldg((const float4*)(xp + j * 8 + 4));
            }
        }
    }

    // ---- stage W hi/lo into smem (L2-resident) ----
    {
        int n = tid >> 1, k0 = (tid & 1) * 64;
        const uint4* shi = (const uint4*)(g_whi + n * 128 + k0);
        const uint4* slo = (const uint4*)(g_wlo + n * 128 + k0);
        uint4* dhi = (uint4*)(smem + SM_WHI + n * (LDS_STRIDE * 2) + k0 * 2);
        uint4* dlo = (uint4*)(smem + SM_WLO + n * (LDS_STRIDE * 2) + k0 * 2);
        #pragma unroll
        for (int j = 0; j < 8; j++) {
            dhi[j] = __ldg(shi + j);
            dlo[j] = __ldg(slo + j);
        }
    }

    // ---- convert X to fp16 and store to smem ----
    {
        int row = tid >> 1, k0 = (tid & 1) * 64;
        char* dhi = smem + SM_XHI + row * (LDS_STRIDE * 2) + k0 * 2;
        #pragma unroll
        for (int j = 0; j < 8; j++) {
            float4 a = xv[2 * j], b = xv[2 * j + 1];
            uint32_t p0 = h2_as_u32(__floats2half2_rn(a.x, a.y));
            uint32_t p1 = h2_as_u32(__floats2half2_rn(a.z, a.w));
            uint32_t p2 = h2_as_u32(__floats2half2_rn(b.x, b.y));
            uint32_t p3 = h2_as_u32(__floats2half2_rn(b.z, b.w));
            *(uint4*)(dhi + j * 16) = make_uint4(p0, p1, p2, p3);
        }
    }
    __syncthreads();

    // ---- warp tile: warp_m in 0..3 (32 rows), warp_n in 0..1 (64 cols) ----
    const int warp_m = wid & 3, warp_n = wid >> 2;
    const int mb = warp_m * 32;
    const int nb = warp_n * 64;

    float acc[2][8][4];
    #pragma unroll
    for (int i = 0; i < 2; i++)
        #pragma unroll
        for (int j = 0; j < 8; j++)
            #pragma unroll
            for (int q = 0; q < 4; q++) acc[i][j][q] = 0.0f;

    const int g = lane >> 3, lr = lane & 7;

    #pragma unroll
    for (int kk = 0; kk < 8; kk++) {
        const int k0 = kk * 16;
        uint32_t ahi[2][4];
        #pragma unroll
        for (int mt = 0; mt < 2; mt++) {
            uint32_t off = (uint32_t)(mb + mt * 16 + (g & 1) * 8 + lr) * (LDS_STRIDE * 2)
                         + (uint32_t)(k0 + (g >> 1) * 8) * 2;
            ldsm_x4(ahi[mt], sb + SM_XHI + off);
        }
        #pragma unroll
        for (int bt = 0; bt < 4; bt++) {
            uint32_t off = (uint32_t)(nb + bt * 16 + (g >> 1) * 8 + lr) * (LDS_STRIDE * 2)
                         + (uint32_t)(k0 + (g & 1) * 8) * 2;
            uint32_t bhi[4], blo[4];
            ldsm_x4(bhi, sb + SM_WHI + off);
            ldsm_x4(blo, sb + SM_WLO + off);
            #pragma unroll
            for (int mt = 0; mt < 2; mt++)
                #pragma unroll
                for (int nt = 0; nt < 2; nt++) {
                    float* c = acc[mt][bt * 2 + nt];
                    mma_fp16(c, ahi[mt], bhi + nt * 2);
                    mma_fp16(c, ahi[mt], blo + nt * 2);
                }
        }
    }

    const int er = lane >> 2, ec2 = (lane & 3) * 2;
    #pragma unroll
    for (int mt = 0; mt < 2; mt++) {
        #pragma unroll
        for (int j = 0; j < 8; j++) {
            int n = nb + j * 8 + ec2;
            int m_lo = m0 + mb + mt * 16 + er;
            int m_hi = m_lo + 8;
            if (m_lo < M)
                *(float2*)(g_h + (size_t)m_lo * 128 + n) =
                    make_float2(acc[mt][j][0], acc[mt][j][1]);
            if (m_hi < M)
                *(float2*)(g_h + (size_t)m_hi * 128 + n) =
                    make_float2(acc[mt][j][2], acc[mt][j][3]);
        }
    }
}

// ---------------------------------------------------------------------------
// SpMM + bias + sigmoid: one warp per row, float4 column slice per lane.
// Vectorized warp-uniform ec/ev loads; 8-edge unroll with real MLP=8
// (launch_bounds minBlocks=2 lets ptxas keep all gathers in flight).
// ---------------------------------------------------------------------------
__device__ __forceinline__ void spmm_edge(
    float4& acc, float v, const float4* hp, int c, int lane)
{
    float4 h = hp[(size_t)c * 32 + lane];
    acc.x = fmaf(v, h.x, acc.x);
    acc.y = fmaf(v, h.y, acc.y);
    acc.z = fmaf(v, h.z, acc.z);
    acc.w = fmaf(v, h.w, acc.w);
}

template <int IS64>
__device__ __forceinline__ void spmm_body(
    const void* ec, const float* ev, const float* bias, float* out, int M)
{
    int row = blockIdx.x * 8 + (threadIdx.x >> 5);
    if (row >= M) return;
    int lane = threadIdx.x & 31;

    int s = __ldg(&g_row_ptr[row]);
    int e = __ldg(&g_row_ptr[row + 1]);

    const float4* hp = (const float4*)g_h;
    float4 acc = make_float4(0, 0, 0, 0);

    int i = s;
    // align to 4-edge boundary for vector ec/ev loads
    while (i < e && (i & 3)) {
        spmm_edge(acc, __ldg(ev + i), hp, load_idx<IS64>(ec, i), lane);
        i++;
    }

    for (; i + 8 <= e; i += 8) {
        int c[8];
        if (IS64) {
            longlong2 q0 = __ldg((const longlong2*)((const long long*)ec + i));
            longlong2 q1 = __ldg((const longlong2*)((const long long*)ec + i + 2));
            longlong2 q2 = __ldg((const longlong2*)((const long long*)ec + i + 4));
            longlong2 q3 = __ldg((const longlong2*)((const long long*)ec + i + 6));
            c[0] = (int)q0.x; c[1] = (int)q0.y; c[2] = (int)q1.x; c[3] = (int)q1.y;
            c[4] = (int)q2.x; c[5] = (int)q2.y; c[6] = (int)q3.x; c[7] = (int)q3.y;
        } else {
            int4 ia = __ldg((const int4*)((const int*)ec + i));
            int4 ib = __ldg((const int4*)((const int*)ec + i + 4));
            c[0] = ia.x; c[1] = ia.y; c[2] = ia.z; c[3] = ia.w;
            c[4] = ib.x; c[5] = ib.y; c[6] = ib.z; c[7] = ib.w;
        }
        float4 va = __ldg((const float4*)(ev + i));
        float4 vb = __ldg((const float4*)(ev + i + 4));
        float v[8] = {va.x, va.y, va.z, va.w, vb.x, vb.y, vb.z, vb.w};

        float4 h[8];
        #pragma unroll
        for (int q = 0; q < 8; q++) h[q] = hp[(size_t)c[q] * 32 + lane];
        #pragma unroll
        for (int q = 0; q < 8; q++) {
            acc.x = fmaf(v[q], h[q].x, acc.x);
            acc.y = fmaf(v[q], h[q].y, acc.y);
            acc.z = fmaf(v[q], h[q].z, acc.z);
            acc.w = fmaf(v[q], h[q].w, acc.w);
        }
    }
    if (i + 4 <= e) {
        int c[4];
        if (IS64) {
            longlong2 q0 = __ldg((const longlong2*)((const long long*)ec + i));
            longlong2 q1 = __ldg((const longlong2*)((const long long*)ec + i + 2));
            c[0] = (int)q0.x; c[1] = (int)q0.y; c[2] = (int)q1.x; c[3] = (int)q1.y;
        } else {
            int4 ia = __ldg((const int4*)((const int*)ec + i));
            c[0] = ia.x; c[1] = ia.y; c[2] = ia.z; c[3] = ia.w;
        }
        float4 va = __ldg((const float4*)(ev + i));
        float v[4] = {va.x, va.y, va.z, va.w};
        float4 h[4];
        #pragma unroll
        for (int q = 0; q < 4; q++) h[q] = hp[(size_t)c[q] * 32 + lane];
        #pragma unroll
        for (int q = 0; q < 4; q++) {
            acc.x = fmaf(v[q], h[q].x, acc.x);
            acc.y = fmaf(v[q], h[q].y, acc.y);
            acc.z = fmaf(v[q], h[q].z, acc.z);
            acc.w = fmaf(v[q], h[q].w, acc.w);
        }
        i += 4;
    }
    for (; i < e; i++)
        spmm_edge(acc, __ldg(ev + i), hp, load_idx<IS64>(ec, i), lane);

    float4 b = __ldg(((const float4*)bias) + lane);
    float4 r;
    r.x = 1.0f / (1.0f + __expf(-(acc.x + b.x)));
    r.y = 1.0f / (1.0f + __expf(-(acc.y + b.y)));
    r.z = 1.0f / (1.0f + __expf(-(acc.z + b.z)));
    r.w = 1.0f / (1.0f + __expf(-(acc.w + b.w)));
    ((float4*)out)[(size_t)row * 32 + lane] = r;
}

__global__ __launch_bounds__(256, 2) void spmm_kernel(
    const void* __restrict__ ec, const float* __restrict__ ev,
    const float* __restrict__ bias, float* __restrict__ out, int M)
{
    if (g_idx64) spmm_body<1>(ec, ev, bias, out, M);
    else         spmm_body<0>(ec, ev, bias, out, M);
}

// ---------------------------------------------------------------------------
// Launch. Inputs: X, edge_row, edge_col, edge_val, weight, bias
// ---------------------------------------------------------------------------
extern "C" void kernel_launch(void* const* d_in, const int* in_sizes, int n_in,
                              void* d_out, int out_size) {
    const float* X    = (const float*)d_in[0];
    const void*  er   = d_in[1];
    const void*  ec   = d_in[2];
    const float* ev   = (const float*)d_in[3];
    const float* W    = (const float*)d_in[4];
    const float* bias = (const float*)d_in[5];
    float* out = (float*)d_out;

    int M = in_sizes[0] / UNITS;     // 100000
    int E = in_sizes[2];             // 1600000

    static int smem_set = 0;
    if (!smem_set) {
        cudaFuncSetAttribute(gemm_hmma_kernel,
                             cudaFuncAttributeMaxDynamicSharedMemorySize, SM_TOTAL);
        smem_set = 1;
    }

    prep_kernel<<<64, 256>>>(W, (const int*)ec);
    rowptr_kernel<<<(E + 256) / 256, 256>>>(er, E, M);
    gemm_hmma_kernel<<<(M + 127) / 128, 256, SM_TOTAL>>>(X, M);
    spmm_kernel<<<(M + 7) / 8, 256>>>(ec, ev, bias, out, M);
}

// round 14
// speedup vs baseline: 1.2364x; 1.2364x over previous
#include <cuda_runtime.h>
#include <cuda_fp16.h>
#include <cstdint>

#define MAX_NODES 100000
#define UNITS 128

// ---------------------------------------------------------------------------
// Scratch (no cudaMalloc allowed)
// ---------------------------------------------------------------------------
__device__ __align__(16) float g_h[(size_t)MAX_NODES * UNITS];  // 51.2 MB
__device__ int   g_row_ptr[MAX_NODES + 1];
__device__ int   g_idx64;
// W as fp16, stored as B[n][k] = W[k][n], row-major [128][128]
__device__ __align__(16) unsigned short g_whi[128 * 128];

__device__ __forceinline__ uint32_t smem_u32(const void* p) {
    uint32_t a;
    asm("{ .reg .u64 t; cvta.to.shared.u64 t, %1; cvt.u32.u64 %0, t; }"
        : "=r"(a) : "l"(p));
    return a;
}

__device__ __forceinline__ uint32_t h2_as_u32(__half2 h) {
    union { __half2 h; uint32_t u; } cvt;
    cvt.h = h;
    return cvt.u;
}

template <int IS64>
__device__ __forceinline__ int load_idx(const void* p, int i) {
    if (IS64) return (int)__ldg(((const long long*)p) + i);
    return __ldg(((const int*)p) + i);
}

// ---------------------------------------------------------------------------
// Fused prep: W -> fp16 image B[n][k]  +  index-dtype probe.
// ---------------------------------------------------------------------------
__global__ void prep_kernel(const float* __restrict__ W, const int* __restrict__ ec) {
    if (blockIdx.x == 0 && threadIdx.x == 0) {
        int nz = 0;
        #pragma unroll
        for (int i = 1; i < 64; i += 2) nz += (ec[i] != 0);
        g_idx64 = (nz == 0) ? 1 : 0;
    }
    int i = blockIdx.x * blockDim.x + threadIdx.x;
    if (i >= 128 * 128) return;
    int n = i >> 7, k = i & 127;
    float w = __ldg(W + (size_t)k * 128 + n);
    g_whi[n * 128 + k] = __half_as_ushort(__float2half_rn(w));
}

// ---------------------------------------------------------------------------
// CSR row_ptr via edge-difference scatter (one pass, coalesced).
// ---------------------------------------------------------------------------
template <int IS64>
__device__ __forceinline__ void rowptr_body(const void* er, int E, int M) {
    int i = blockIdx.x * blockDim.x + threadIdx.x;
    if (i > E) return;
    if (i == E) {
        int last = load_idx<IS64>(er, E - 1);
        for (int r = last + 1; r <= M; r++) g_row_ptr[r] = E;
        return;
    }
    int r1 = load_idx<IS64>(er, i);
    int r0 = (i == 0) ? -1 : load_idx<IS64>(er, i - 1);
    for (int r = r0 + 1; r <= r1; r++) g_row_ptr[r] = i;
}

__global__ void rowptr_kernel(const void* __restrict__ er, int E, int M) {
    if (g_idx64) rowptr_body<1>(er, E, M);
    else         rowptr_body<0>(er, E, M);
}

// ---------------------------------------------------------------------------
// HMMA GEMM: g_h[M,128] = X[M,128] @ W[128,128]
// fp16 1-pass (X and W rounded to fp16), fp32 accum, mma.sync.m16n8k16.
// CTA tile 128x128, 256 threads = 8 warps (4m x 2n).
// smem 69.6KB -> 3 CTA/SM. X DRAM loads hoisted above W (L2) staging.
// ---------------------------------------------------------------------------
#define LDS_STRIDE 136                  // 272B rows = 17*16B, conflict-free
#define TILE_BYTES (128 * LDS_STRIDE * 2)
#define SM_XHI 0
#define SM_WHI (SM_XHI + TILE_BYTES)
#define SM_TOTAL (SM_WHI + TILE_BYTES)

__device__ __forceinline__ void ldsm_x4(uint32_t* r, uint32_t addr) {
    asm volatile("ldmatrix.sync.aligned.m8n8.x4.shared.b16 {%0,%1,%2,%3}, [%4];"
                 : "=r"(r[0]), "=r"(r[1]), "=r"(r[2]), "=r"(r[3]) : "r"(addr));
}
__device__ __forceinline__ void mma_fp16(float* c, const uint32_t* a, const uint32_t* b) {
    asm volatile(
        "mma.sync.aligned.m16n8k16.row.col.f32.f16.f16.f32 "
        "{%0,%1,%2,%3}, {%4,%5,%6,%7}, {%8,%9}, {%0,%1,%2,%3};"
        : "+f"(c[0]), "+f"(c[1]), "+f"(c[2]), "+f"(c[3])
        : "r"(a[0]), "r"(a[1]), "r"(a[2]), "r"(a[3]), "r"(b[0]), "r"(b[1]));
}

__global__ __launch_bounds__(256, 3)
void gemm_hmma_kernel(const float* __restrict__ X, int M)
{
    extern __shared__ char smem[];
    const uint32_t sb = smem_u32(smem);
    const int tid = threadIdx.x;
    const int wid = tid >> 5, lane = tid & 31;
    const int m0 = blockIdx.x * 128;

    // ---- issue X DRAM loads first (16 float4 in flight) ----
    float4 xv[16];
    {
        int row = tid >> 1, k0 = (tid & 1) * 64;
        bool valid = (m0 + row) < M;
        const float* xp = X + (size_t)(m0 + row) * 128 + k0;
        #pragma unroll
        for (int j = 0; j < 8; j++) {
            xv[2 * j]     = make_float4(0, 0, 0, 0);
            xv[2 * j + 1] = make_float4(0, 0, 0, 0);
            if (valid) {
                xv[2 * j]     = __ldg((const float4*)(xp + j * 8));
                xv[2 * j + 1] = __ldg((const float4*)(xp + j * 8 + 4));
            }
        }
    }

    // ---- stage W into smem (L2-resident) ----
    {
        int n = tid >> 1, k0 = (tid & 1) * 64;
        const uint4* shi = (const uint4*)(g_whi + n * 128 + k0);
        uint4* dhi = (uint4*)(smem + SM_WHI + n * (LDS_STRIDE * 2) + k0 * 2);
        #pragma unroll
        for (int j = 0; j < 8; j++) dhi[j] = __ldg(shi + j);
    }

    // ---- convert X to fp16 and store to smem ----
    {
        int row = tid >> 1, k0 = (tid & 1) * 64;
        char* dhi = smem + SM_XHI + row * (LDS_STRIDE * 2) + k0 * 2;
        #pragma unroll
        for (int j = 0; j < 8; j++) {
            float4 a = xv[2 * j], b = xv[2 * j + 1];
            uint32_t p0 = h2_as_u32(__floats2half2_rn(a.x, a.y));
            uint32_t p1 = h2_as_u32(__floats2half2_rn(a.z, a.w));
            uint32_t p2 = h2_as_u32(__floats2half2_rn(b.x, b.y));
            uint32_t p3 = h2_as_u32(__floats2half2_rn(b.z, b.w));
            *(uint4*)(dhi + j * 16) = make_uint4(p0, p1, p2, p3);
        }
    }
    __syncthreads();

    // ---- warp tile: warp_m in 0..3 (32 rows), warp_n in 0..1 (64 cols) ----
    const int warp_m = wid & 3, warp_n = wid >> 2;
    const int mb = warp_m * 32;
    const int nb = warp_n * 64;

    float acc[2][8][4];
    #pragma unroll
    for (int i = 0; i < 2; i++)
        #pragma unroll
        for (int j = 0; j < 8; j++)
            #pragma unroll
            for (int q = 0; q < 4; q++) acc[i][j][q] = 0.0f;

    const int g = lane >> 3, lr = lane & 7;

    #pragma unroll
    for (int kk = 0; kk < 8; kk++) {
        const int k0 = kk * 16;
        uint32_t ahi[2][4];
        #pragma unroll
        for (int mt = 0; mt < 2; mt++) {
            uint32_t off = (uint32_t)(mb + mt * 16 + (g & 1) * 8 + lr) * (LDS_STRIDE * 2)
                         + (uint32_t)(k0 + (g >> 1) * 8) * 2;
            ldsm_x4(ahi[mt], sb + SM_XHI + off);
        }
        #pragma unroll
        for (int bt = 0; bt < 4; bt++) {
            uint32_t off = (uint32_t)(nb + bt * 16 + (g >> 1) * 8 + lr) * (LDS_STRIDE * 2)
                         + (uint32_t)(k0 + (g & 1) * 8) * 2;
            uint32_t bhi[4];
            ldsm_x4(bhi, sb + SM_WHI + off);
            #pragma unroll
            for (int mt = 0; mt < 2; mt++)
                #pragma unroll
                for (int nt = 0; nt < 2; nt++)
                    mma_fp16(acc[mt][bt * 2 + nt], ahi[mt], bhi + nt * 2);
        }
    }

    const int er = lane >> 2, ec2 = (lane & 3) * 2;
    #pragma unroll
    for (int mt = 0; mt < 2; mt++) {
        #pragma unroll
        for (int j = 0; j < 8; j++) {
            int n = nb + j * 8 + ec2;
            int m_lo = m0 + mb + mt * 16 + er;
            int m_hi = m_lo + 8;
            if (m_lo < M)
                *(float2*)(g_h + (size_t)m_lo * 128 + n) =
                    make_float2(acc[mt][j][0], acc[mt][j][1]);
            if (m_hi < M)
                *(float2*)(g_h + (size_t)m_hi * 128 + n) =
                    make_float2(acc[mt][j][2], acc[mt][j][3]);
        }
    }
}

// ---------------------------------------------------------------------------
// SpMM + bias + sigmoid: one warp per row, float4 column slice per lane
// (one LDG.128 per edge per lane). 8-edge unroll, fp32 accumulation.
// EXACT R11 form (regs=32, occ ~83%): warp-count is the latency hider.
// ---------------------------------------------------------------------------
template <int IS64>
__device__ __forceinline__ void spmm_body(
    const void* ec, const float* ev, const float* bias, float* out, int M)
{
    int row = blockIdx.x * 8 + (threadIdx.x >> 5);
    if (row >= M) return;
    int lane = threadIdx.x & 31;

    int s = __ldg(&g_row_ptr[row]);
    int e = __ldg(&g_row_ptr[row + 1]);

    const float4* hp = (const float4*)g_h;
    float4 acc = make_float4(0, 0, 0, 0);

    int i = s;
    for (; i + 8 <= e; i += 8) {
        int   c[8];
        float v[8];
        #pragma unroll
        for (int q = 0; q < 8; q++) {
            c[q] = load_idx<IS64>(ec, i + q);
            v[q] = __ldg(ev + i + q);
        }
        float4 h[8];
        #pragma unroll
        for (int q = 0; q < 8; q++) h[q] = hp[(size_t)c[q] * 32 + lane];
        #pragma unroll
        for (int q = 0; q < 8; q++) {
            acc.x = fmaf(v[q], h[q].x, acc.x);
            acc.y = fmaf(v[q], h[q].y, acc.y);
            acc.z = fmaf(v[q], h[q].z, acc.z);
            acc.w = fmaf(v[q], h[q].w, acc.w);
        }
    }
    if (i + 4 <= e) {
        int   c[4];
        float v[4];
        #pragma unroll
        for (int q = 0; q < 4; q++) {
            c[q] = load_idx<IS64>(ec, i + q);
            v[q] = __ldg(ev + i + q);
        }
        float4 h[4];
        #pragma unroll
        for (int q = 0; q < 4; q++) h[q] = hp[(size_t)c[q] * 32 + lane];
        #pragma unroll
        for (int q = 0; q < 4; q++) {
            acc.x = fmaf(v[q], h[q].x, acc.x);
            acc.y = fmaf(v[q], h[q].y, acc.y);
            acc.z = fmaf(v[q], h[q].z, acc.z);
            acc.w = fmaf(v[q], h[q].w, acc.w);
        }
        i += 4;
    }
    for (; i < e; i++) {
        int c0 = load_idx<IS64>(ec, i);
        float v0 = __ldg(ev + i);
        float4 h0 = hp[(size_t)c0 * 32 + lane];
        acc.x = fmaf(v0, h0.x, acc.x); acc.y = fmaf(v0, h0.y, acc.y);
        acc.z = fmaf(v0, h0.z, acc.z); acc.w = fmaf(v0, h0.w, acc.w);
    }

    float4 b = __ldg(((const float4*)bias) + lane);
    float4 r;
    r.x = 1.0f / (1.0f + __expf(-(acc.x + b.x)));
    r.y = 1.0f / (1.0f + __expf(-(acc.y + b.y)));
    r.z = 1.0f / (1.0f + __expf(-(acc.z + b.z)));
    r.w = 1.0f / (1.0f + __expf(-(acc.w + b.w)));
    ((float4*)out)[(size_t)row * 32 + lane] = r;
}

__global__ __launch_bounds__(256) void spmm_kernel(
    const void* __restrict__ ec, const float* __restrict__ ev,
    const float* __restrict__ bias, float* __restrict__ out, int M)
{
    if (g_idx64) spmm_body<1>(ec, ev, bias, out, M);
    else         spmm_body<0>(ec, ev, bias, out, M);
}

// ---------------------------------------------------------------------------
// Launch. Inputs: X, edge_row, edge_col, edge_val, weight, bias
// ---------------------------------------------------------------------------
extern "C" void kernel_launch(void* const* d_in, const int* in_sizes, int n_in,
                              void* d_out, int out_size) {
    const float* X    = (const float*)d_in[0];
    const void*  er   = d_in[1];
    const void*  ec   = d_in[2];
    const float* ev   = (const float*)d_in[3];
    const float* W    = (const float*)d_in[4];
    const float* bias = (const float*)d_in[5];
    float* out = (float*)d_out;

    int M = in_sizes[0] / UNITS;     // 100000
    int E = in_sizes[2];             // 1600000

    static int smem_set = 0;
    if (!smem_set) {
        cudaFuncSetAttribute(gemm_hmma_kernel,
                             cudaFuncAttributeMaxDynamicSharedMemorySize, SM_TOTAL);
        smem_set = 1;
    }

    prep_kernel<<<64, 256>>>(W, (const int*)ec);
    rowptr_kernel<<<(E + 256) / 256, 256>>>(er, E, M);
    gemm_hmma_kernel<<<(M + 127) / 128, 256, SM_TOTAL>>>(X, M);
    spmm_kernel<<<(M + 7) / 8, 256>>>(ec, ev, bias, out, M);
}

// round 15
// speedup vs baseline: 1.4981x; 1.2116x over previous
#include <cuda_runtime.h>
#include <cuda_fp16.h>
#include <cstdint>

#define MAX_NODES 100000
#define UNITS 128

// ---------------------------------------------------------------------------
// Scratch (no cudaMalloc allowed)
// ---------------------------------------------------------------------------
__device__ __align__(16) float g_h[(size_t)MAX_NODES * UNITS];       // 51.2 MB
__device__ __align__(16) unsigned short g_xh[(size_t)MAX_NODES * UNITS]; // 25.6 MB fp16 X
__device__ int   g_row_ptr[MAX_NODES + 1];
__device__ int   g_idx64;
// W as fp16, stored as B[n][k] = W[k][n], row-major [128][128]
__device__ __align__(16) unsigned short g_whi[128 * 128];

__device__ __forceinline__ uint32_t smem_u32(const void* p) {
    uint32_t a;
    asm("{ .reg .u64 t; cvta.to.shared.u64 t, %1; cvt.u32.u64 %0, t; }"
        : "=r"(a) : "l"(p));
    return a;
}

__device__ __forceinline__ uint32_t h2_as_u32(__half2 h) {
    union { __half2 h; uint32_t u; } cvt;
    cvt.h = h;
    return cvt.u;
}

template <int IS64>
__device__ __forceinline__ int load_idx(const void* p, int i) {
    if (IS64) return (int)__ldg(((const long long*)p) + i);
    return __ldg(((const int*)p) + i);
}

// ---------------------------------------------------------------------------
// prep: W -> fp16 image B[n][k]  +  index-dtype probe.
// ---------------------------------------------------------------------------
__global__ void prep_kernel(const float* __restrict__ W, const int* __restrict__ ec) {
    if (blockIdx.x == 0 && threadIdx.x == 0) {
        int nz = 0;
        #pragma unroll
        for (int i = 1; i < 64; i += 2) nz += (ec[i] != 0);
        g_idx64 = (nz == 0) ? 1 : 0;
    }
    int i = blockIdx.x * blockDim.x + threadIdx.x;
    if (i >= 128 * 128) return;
    int n = i >> 7, k = i & 127;
    float w = __ldg(W + (size_t)k * 128 + n);
    g_whi[n * 128 + k] = __half_as_ushort(__float2half_rn(w));
}

// ---------------------------------------------------------------------------
// mid: fused  (a) CSR row_ptr edge-diff scatter  (b) X -> fp16 conversion.
// Low blocks do (a), high blocks do (b) — overlapped memory-bound streams.
// ---------------------------------------------------------------------------
template <int IS64>
__device__ __forceinline__ void rowptr_part(const void* er, int E, int M, int bid) {
    int i = bid * blockDim.x + threadIdx.x;
    if (i > E) return;
    if (i == E) {
        int last = load_idx<IS64>(er, E - 1);
        for (int r = last + 1; r <= M; r++) g_row_ptr[r] = E;
        return;
    }
    int r1 = load_idx<IS64>(er, i);
    int r0 = (i == 0) ? -1 : load_idx<IS64>(er, i - 1);
    for (int r = r0 + 1; r <= r1; r++) g_row_ptr[r] = i;
}

__global__ void mid_kernel(const void* __restrict__ er, int E, int M,
                           const float* __restrict__ X, int rb, int items)
{
    int bid = blockIdx.x;
    if (bid < rb) {
        if (g_idx64) rowptr_part<1>(er, E, M, bid);
        else         rowptr_part<0>(er, E, M, bid);
        return;
    }
    // X conversion: item j converts 8 floats -> 8 halves (one uint4 store)
    int j = (bid - rb) * blockDim.x + threadIdx.x;
    if (j >= items) return;
    const float4* src = (const float4*)X + (size_t)j * 2;
    float4 a = __ldg(src);
    float4 b = __ldg(src + 1);
    uint4 o;
    o.x = h2_as_u32(__floats2half2_rn(a.x, a.y));
    o.y = h2_as_u32(__floats2half2_rn(a.z, a.w));
    o.z = h2_as_u32(__floats2half2_rn(b.x, b.y));
    o.w = h2_as_u32(__floats2half2_rn(b.z, b.w));
    ((uint4*)g_xh)[j] = o;
}

// ---------------------------------------------------------------------------
// HMMA GEMM: g_h[M,128] = Xh[M,128] @ W[128,128]   (both already fp16)
// cp.async tile staging (no conversion, no register prefetch), fp32 accum,
// mma.sync.m16n8k16. CTA 128x128, 256 thr = 8 warps (4m x 2n), 3 CTA/SM.
// ---------------------------------------------------------------------------
#define LDS_STRIDE 136                  // 272B rows = 17*16B, conflict-free
#define TILE_BYTES (128 * LDS_STRIDE * 2)
#define SM_XHI 0
#define SM_WHI (SM_XHI + TILE_BYTES)
#define SM_TOTAL (SM_WHI + TILE_BYTES)

__device__ __forceinline__ void cp_async16(uint32_t dst, const void* src) {
    asm volatile("cp.async.ca.shared.global [%0], [%1], 16;"
                 :: "r"(dst), "l"(__cvta_generic_to_global(src)) : "memory");
}
__device__ __forceinline__ void cp_async_wait_all() {
    asm volatile("cp.async.commit_group;\n\tcp.async.wait_group 0;" ::: "memory");
}
__device__ __forceinline__ void ldsm_x4(uint32_t* r, uint32_t addr) {
    asm volatile("ldmatrix.sync.aligned.m8n8.x4.shared.b16 {%0,%1,%2,%3}, [%4];"
                 : "=r"(r[0]), "=r"(r[1]), "=r"(r[2]), "=r"(r[3]) : "r"(addr));
}
__device__ __forceinline__ void mma_fp16(float* c, const uint32_t* a, const uint32_t* b) {
    asm volatile(
        "mma.sync.aligned.m16n8k16.row.col.f32.f16.f16.f32 "
        "{%0,%1,%2,%3}, {%4,%5,%6,%7}, {%8,%9}, {%0,%1,%2,%3};"
        : "+f"(c[0]), "+f"(c[1]), "+f"(c[2]), "+f"(c[3])
        : "r"(a[0]), "r"(a[1]), "r"(a[2]), "r"(a[3]), "r"(b[0]), "r"(b[1]));
}

__global__ __launch_bounds__(256, 3)
void gemm_hmma_kernel(int M)
{
    extern __shared__ char smem[];
    const uint32_t sb = smem_u32(smem);
    const int tid = threadIdx.x;
    const int wid = tid >> 5, lane = tid & 31;
    const int m0 = blockIdx.x * 128;
    const int mrows = min(128, M - m0);

    // ---- stage A (fp16 X rows) + W via cp.async: 16B chunks ----
    // A: 128 rows x 16 chunks; thread t handles chunk ids t, t+256, ...
    {
        #pragma unroll
        for (int i = 0; i < 8; i++) {
            int cid = tid + i * 256;
            int r = cid >> 4, j = cid & 15;
            if (r < mrows)
                cp_async16(sb + SM_XHI + r * (LDS_STRIDE * 2) + j * 16,
                           g_xh + (size_t)(m0 + r) * 128 + j * 8);
        }
        #pragma unroll
        for (int i = 0; i < 8; i++) {
            int cid = tid + i * 256;
            int r = cid >> 4, j = cid & 15;
            cp_async16(sb + SM_WHI + r * (LDS_STRIDE * 2) + j * 16,
                       g_whi + r * 128 + j * 8);
        }
        // zero-fill A rows beyond M (avoid stale smem feeding MMA)
        if (mrows < 128) {
            for (int cid = tid; cid < 2048; cid += 256) {
                int r = cid >> 4, j = cid & 15;
                if (r >= mrows)
                    *(uint4*)(smem + SM_XHI + r * (LDS_STRIDE * 2) + j * 16) =
                        make_uint4(0, 0, 0, 0);
            }
        }
        cp_async_wait_all();
    }
    __syncthreads();

    // ---- warp tile: warp_m in 0..3 (32 rows), warp_n in 0..1 (64 cols) ----
    const int warp_m = wid & 3, warp_n = wid >> 2;
    const int mb = warp_m * 32;
    const int nb = warp_n * 64;

    float acc[2][8][4];
    #pragma unroll
    for (int i = 0; i < 2; i++)
        #pragma unroll
        for (int j = 0; j < 8; j++)
            #pragma unroll
            for (int q = 0; q < 4; q++) acc[i][j][q] = 0.0f;

    const int g = lane >> 3, lr = lane & 7;

    #pragma unroll
    for (int kk = 0; kk < 8; kk++) {
        const int k0 = kk * 16;
        uint32_t ahi[2][4];
        #pragma unroll
        for (int mt = 0; mt < 2; mt++) {
            uint32_t off = (uint32_t)(mb + mt * 16 + (g & 1) * 8 + lr) * (LDS_STRIDE * 2)
                         + (uint32_t)(k0 + (g >> 1) * 8) * 2;
            ldsm_x4(ahi[mt], sb + SM_XHI + off);
        }
        #pragma unroll
        for (int bt = 0; bt < 4; bt++) {
            uint32_t off = (uint32_t)(nb + bt * 16 + (g >> 1) * 8 + lr) * (LDS_STRIDE * 2)
                         + (uint32_t)(k0 + (g & 1) * 8) * 2;
            uint32_t bhi[4];
            ldsm_x4(bhi, sb + SM_WHI + off);
            #pragma unroll
            for (int mt = 0; mt < 2; mt++)
                #pragma unroll
                for (int nt = 0; nt < 2; nt++)
                    mma_fp16(acc[mt][bt * 2 + nt], ahi[mt], bhi + nt * 2);
        }
    }

    const int er = lane >> 2, ec2 = (lane & 3) * 2;
    #pragma unroll
    for (int mt = 0; mt < 2; mt++) {
        #pragma unroll
        for (int j = 0; j < 8; j++) {
            int n = nb + j * 8 + ec2;
            int m_lo = m0 + mb + mt * 16 + er;
            int m_hi = m_lo + 8;
            if (m_lo < M)
                *(float2*)(g_h + (size_t)m_lo * 128 + n) =
                    make_float2(acc[mt][j][0], acc[mt][j][1]);
            if (m_hi < M)
                *(float2*)(g_h + (size_t)m_hi * 128 + n) =
                    make_float2(acc[mt][j][2], acc[mt][j][3]);
        }
    }
}

// ---------------------------------------------------------------------------
// SpMM + bias + sigmoid: one warp per row, float4 column slice per lane
// (one LDG.128 per edge per lane). 8-edge unroll, fp32 accumulation.
// EXACT R11/R14 form (regs=32, occ ~83%): warp-count is the latency hider.
// ---------------------------------------------------------------------------
template <int IS64>
__device__ __forceinline__ void spmm_body(
    const void* ec, const float* ev, const float* bias, float* out, int M)
{
    int row = blockIdx.x * 8 + (threadIdx.x >> 5);
    if (row >= M) return;
    int lane = threadIdx.x & 31;

    int s = __ldg(&g_row_ptr[row]);
    int e = __ldg(&g_row_ptr[row + 1]);

    const float4* hp = (const float4*)g_h;
    float4 acc = make_float4(0, 0, 0, 0);

    int i = s;
    for (; i + 8 <= e; i += 8) {
        int   c[8];
        float v[8];
        #pragma unroll
        for (int q = 0; q < 8; q++) {
            c[q] = load_idx<IS64>(ec, i + q);
            v[q] = __ldg(ev + i + q);
        }
        float4 h[8];
        #pragma unroll
        for (int q = 0; q < 8; q++) h[q] = hp[(size_t)c[q] * 32 + lane];
        #pragma unroll
        for (int q = 0; q < 8; q++) {
            acc.x = fmaf(v[q], h[q].x, acc.x);
            acc.y = fmaf(v[q], h[q].y, acc.y);
            acc.z = fmaf(v[q], h[q].z, acc.z);
            acc.w = fmaf(v[q], h[q].w, acc.w);
        }
    }
    if (i + 4 <= e) {
        int   c[4];
        float v[4];
        #pragma unroll
        for (int q = 0; q < 4; q++) {
            c[q] = load_idx<IS64>(ec, i + q);
            v[q] = __ldg(ev + i + q);
        }
        float4 h[4];
        #pragma unroll
        for (int q = 0; q < 4; q++) h[q] = hp[(size_t)c[q] * 32 + lane];
        #pragma unroll
        for (int q = 0; q < 4; q++) {
            acc.x = fmaf(v[q], h[q].x, acc.x);
            acc.y = fmaf(v[q], h[q].y, acc.y);
            acc.z = fmaf(v[q], h[q].z, acc.z);
            acc.w = fmaf(v[q], h[q].w, acc.w);
        }
        i += 4;
    }
    for (; i < e; i++) {
        int c0 = load_idx<IS64>(ec, i);
        float v0 = __ldg(ev + i);
        float4 h0 = hp[(size_t)c0 * 32 + lane];
        acc.x = fmaf(v0, h0.x, acc.x); acc.y = fmaf(v0, h0.y, acc.y);
        acc.z = fmaf(v0, h0.z, acc.z); acc.w = fmaf(v0, h0.w, acc.w);
    }

    float4 b = __ldg(((const float4*)bias) + lane);
    float4 r;
    r.x = 1.0f / (1.0f + __expf(-(acc.x + b.x)));
    r.y = 1.0f / (1.0f + __expf(-(acc.y + b.y)));
    r.z = 1.0f / (1.0f + __expf(-(acc.z + b.z)));
    r.w = 1.0f / (1.0f + __expf(-(acc.w + b.w)));
    ((float4*)out)[(size_t)row * 32 + lane] = r;
}

__global__ __launch_bounds__(256) void spmm_kernel(
    const void* __restrict__ ec, const float* __restrict__ ev,
    const float* __restrict__ bias, float* __restrict__ out, int M)
{
    if (g_idx64) spmm_body<1>(ec, ev, bias, out, M);
    else         spmm_body<0>(ec, ev, bias, out, M);
}

// ---------------------------------------------------------------------------
// Launch. Inputs: X, edge_row, edge_col, edge_val, weight, bias
// ---------------------------------------------------------------------------
extern "C" void kernel_launch(void* const* d_in, const int* in_sizes, int n_in,
                              void* d_out, int out_size) {
    const float* X    = (const float*)d_in[0];
    const void*  er   = d_in[1];
    const void*  ec   = d_in[2];
    const float* ev   = (const float*)d_in[3];
    const float* W    = (const float*)d_in[4];
    const float* bias = (const float*)d_in[5];
    float* out = (float*)d_out;

    int M = in_sizes[0] / UNITS;     // 100000
    int E = in_sizes[2];             // 1600000

    static int smem_set = 0;
    if (!smem_set) {
        cudaFuncSetAttribute(gemm_hmma_kernel,
                             cudaFuncAttributeMaxDynamicSharedMemorySize, SM_TOTAL);
        smem_set = 1;
    }

    int rb = (E + 1 + 255) / 256;            // rowptr blocks
    int items = (M * UNITS) / 8;             // 8-float conversion items
    int xb = (items + 255) / 256;            // xprep blocks

    prep_kernel<<<64, 256>>>(W, (const int*)ec);
    mid_kernel<<<rb + xb, 256>>>(er, E, M, X, rb, items);
    gemm_hmma_kernel<<<(M + 127) / 128, 256, SM_TOTAL>>>(M);
    spmm_kernel<<<(M + 7) / 8, 256>>>(ec, ev, bias, out, M);
}